// round 2
// baseline (speedup 1.0000x reference)
#include <cuda_runtime.h>
#include <cuda_bf16.h>
#include <math.h>

#define NN     16384
#define EE     262144
#define HIDD   128
#define NG     50
#define NIT    6
#define KNOTS  4096
#define KPB    32

#define LOG2_F 0.6931471805599453f

// ---------------- scratch (device globals; no allocation allowed) ----------
static __device__ float g_d[EE];                       // edge distances
static __device__ float g_table[NIT * KNOTS * HIDD];   // Wfilt(d)*C(d) tables, 12.6 MB
static __device__ float g_h[NN * HIDD];
static __device__ float g_x[NN * HIDD];
static __device__ float g_agg[NN * HIDD];
static __device__ float g_sum;

__device__ __forceinline__ float sspf(float x) {
    // shifted softplus: log(1+exp(x)) - log(2), numerically stable
    return fmaxf(x, 0.0f) + log1pf(expf(-fabsf(x))) - LOG2_F;
}

// ---------------- prep: distances, embedding gather ------------------------
__global__ void k_prep(const float* __restrict__ pos, const int* __restrict__ ei,
                       const int* __restrict__ z, const float* __restrict__ emb)
{
    int t = blockIdx.x * blockDim.x + threadIdx.x;
    int stride = gridDim.x * blockDim.x;
    if (t == 0) g_sum = 0.0f;
    for (int e = t; e < EE; e += stride) {
        int s = ei[e], d = ei[EE + e];
        float dx = pos[3 * s + 0] - pos[3 * d + 0];
        float dy = pos[3 * s + 1] - pos[3 * d + 1];
        float dz = pos[3 * s + 2] - pos[3 * d + 2];
        g_d[e] = sqrtf(dx * dx + dy * dy + dz * dz);
    }
    for (int idx = t; idx < NN * HIDD; idx += stride) {
        g_h[idx] = emb[z[idx >> 7] * HIDD + (idx & 127)];
    }
}

// ---------------- filter table build: Wfilt_i(knot) * C(knot) --------------
__global__ void k_table(const float* __restrict__ Wf1, const float* __restrict__ bf1,
                        const float* __restrict__ Wf2, const float* __restrict__ bf2)
{
    extern __shared__ float sm[];
    float* Wf2s = sm;                 // 128*128
    float* Wf1s = sm + 16384;         // 50*128
    float* eaS  = sm + 16384 + 6400;  // 64
    float* hidS = eaS + 64;           // 128

    const int chunks = KNOTS / KPB;
    int i     = blockIdx.x / chunks;
    int chunk = blockIdx.x % chunks;
    int tx = threadIdx.x;

    const float* Wf1g = Wf1 + i * NG * HIDD;
    const float* Wf2g = Wf2 + i * HIDD * HIDD;
    for (int k = tx; k < NG * HIDD; k += 128)   Wf1s[k] = Wf1g[k];
    for (int k = tx; k < HIDD * HIDD; k += 128) Wf2s[k] = Wf2g[k];
    float bf1v = bf1[i * HIDD + tx];
    float bf2v = bf2[i * HIDD + tx];
    __syncthreads();

    const float DELTA = 10.0f / 49.0f;
    const float COEFF = -0.5f / (DELTA * DELTA);
    const float KSTEP = 10.0f / (float)(KNOTS - 1);

    for (int kk = 0; kk < KPB; kk++) {
        int knot = chunk * KPB + kk;
        float xk = knot * KSTEP;
        if (tx < NG) {
            float dd = xk - tx * DELTA;
            eaS[tx] = expf(COEFF * dd * dd);
        }
        __syncthreads();
        float acc = bf1v;
        #pragma unroll
        for (int g = 0; g < NG; g++) acc += eaS[g] * Wf1s[g * HIDD + tx];
        hidS[tx] = sspf(acc);
        __syncthreads();
        float acc2 = bf2v;
        #pragma unroll 16
        for (int k = 0; k < HIDD; k++) acc2 += hidS[k] * Wf2s[k * HIDD + tx];
        float Cx = 0.5f * (cosf(xk * 0.31415926535897932f) + 1.0f);
        g_table[(i * KNOTS + knot) * HIDD + tx] = acc2 * Cx;
        __syncthreads();
    }
}

// ---------------- 128x128 GEMM, row-tile 32, 256 threads -------------------
// Thread (eg,cg): rows eg*4..eg*4+3, cols cg*4..cg*4+3 (one float4 of cols).
// Weight loads are LDS.128 (conflict-free), A loads are warp broadcasts.
// MODE 0: out = A@W            (no bias)  + zero zbuf tile
// MODE 1: out = ssp(A@W + b)
// MODE 2: out += A@W + b
template <int MODE>
__global__ void k_gemm(const float* __restrict__ A, const float* __restrict__ W,
                       const float* __restrict__ bias, float* __restrict__ out,
                       float* __restrict__ zbuf)
{
    extern __shared__ float sm[];
    float* Ws = sm;           // 128*128  (row-major [k][col])
    float* As = sm + 16384;   // 32*128   (row-major [row][k])
    int tx = threadIdx.x;

    {   // load W (4096 float4)
        float4* Wd = (float4*)Ws;
        const float4* Wg = (const float4*)W;
        #pragma unroll
        for (int i = 0; i < 16; i++) Wd[tx + 256 * i] = Wg[tx + 256 * i];
    }
    int tile = blockIdx.x;  // grid == NN/32
    {   // load A tile (1024 float4)
        float4* Ad = (float4*)As;
        const float4* Ag = (const float4*)(A + tile * 32 * HIDD);
        #pragma unroll
        for (int i = 0; i < 4; i++) Ad[tx + 256 * i] = Ag[tx + 256 * i];
    }
    __syncthreads();

    int cg = tx & 31;   // column quad: cols cg*4 .. cg*4+3
    int eg = tx >> 5;   // row group: rows eg*4 + t
    const float4* Ws4 = (const float4*)Ws;   // [k][32 quads]
    const float*  Ar  = As + (eg * 4) * HIDD;

    float4 acc[4];
    #pragma unroll
    for (int t = 0; t < 4; t++) acc[t] = make_float4(0.f, 0.f, 0.f, 0.f);

    #pragma unroll 8
    for (int k = 0; k < HIDD; k++) {
        float4 w = Ws4[k * 32 + cg];
        #pragma unroll
        for (int t = 0; t < 4; t++) {
            float a = Ar[t * HIDD + k];
            acc[t].x = fmaf(a, w.x, acc[t].x);
            acc[t].y = fmaf(a, w.y, acc[t].y);
            acc[t].z = fmaf(a, w.z, acc[t].z);
            acc[t].w = fmaf(a, w.w, acc[t].w);
        }
    }

    float4 b4 = make_float4(0.f, 0.f, 0.f, 0.f);
    if (MODE > 0) b4 = ((const float4*)bias)[cg];

    #pragma unroll
    for (int t = 0; t < 4; t++) {
        int r = tile * 32 + eg * 4 + t;
        float4* o4 = (float4*)(out + r * HIDD) + cg;
        float4 v = acc[t];
        if (MODE == 0) {
            *o4 = v;
        } else if (MODE == 1) {
            float4 r4;
            r4.x = sspf(v.x + b4.x); r4.y = sspf(v.y + b4.y);
            r4.z = sspf(v.z + b4.z); r4.w = sspf(v.w + b4.w);
            *o4 = r4;
        } else {
            float4 p = *o4;
            p.x += v.x + b4.x; p.y += v.y + b4.y;
            p.z += v.z + b4.z; p.w += v.w + b4.w;
            *o4 = p;
        }
    }
    if (MODE == 0) {
        float4* zb = (float4*)(zbuf + tile * 32 * HIDD);
        float4 z4 = make_float4(0.f, 0.f, 0.f, 0.f);
        #pragma unroll
        for (int i = 0; i < 4; i++) zb[tx + 256 * i] = z4;
    }
}

// ---------------- edge kernel: lerp filter, gather x[src], scatter agg[dst]
__global__ void k_edge(const int* __restrict__ ei, const float* __restrict__ tab)
{
    int gw   = (blockIdx.x * blockDim.x + threadIdx.x) >> 5;
    int lane = threadIdx.x & 31;
    int nw   = (gridDim.x * blockDim.x) >> 5;
    const float scale = (float)(KNOTS - 1) / 10.0f;

    for (int e = gw; e < EE; e += nw) {
        float d = __ldg(&g_d[e]);
        float u = d * scale;
        int i0 = (int)u;
        if (i0 > KNOTS - 2) i0 = KNOTS - 2;
        float f = u - (float)i0;

        int s   = __ldg(&ei[e]);
        int dst = __ldg(&ei[EE + e]);

        const float4* t0 = (const float4*)(tab + i0 * HIDD);
        const float4* xr = (const float4*)(g_x + s * HIDD);
        float4 w0 = t0[lane];
        float4 w1 = t0[lane + 32];   // next knot row
        float4 xv = xr[lane];

        float4 m;
        m.x = fmaf(f, w1.x - w0.x, w0.x) * xv.x;
        m.y = fmaf(f, w1.y - w0.y, w0.y) * xv.y;
        m.z = fmaf(f, w1.z - w0.z, w0.z) * xv.z;
        m.w = fmaf(f, w1.w - w0.w, w0.w) * xv.w;

        float* ar = g_agg + dst * HIDD + lane * 4;
        asm volatile("red.global.add.v4.f32 [%0], {%1, %2, %3, %4};"
                     :: "l"(ar), "f"(m.x), "f"(m.y), "f"(m.z), "f"(m.w)
                     : "memory");
    }
}

// ---------------- readout: per-node MLP + global sum -----------------------
__global__ void k_readout(const float* __restrict__ Wo1, const float* __restrict__ bo1,
                          const float* __restrict__ Wo2, const float* __restrict__ bo2)
{
    __shared__ float Wo1s[HIDD * 64];
    __shared__ float Wo2s[64];
    __shared__ float bo1s[64];
    int tx = threadIdx.x;
    for (int k = tx; k < HIDD * 64; k += 256) Wo1s[k] = Wo1[k];
    if (tx < 64) { Wo2s[tx] = Wo2[tx]; bo1s[tx] = bo1[tx]; }
    __syncthreads();

    int lane = tx & 31;
    int gw   = (blockIdx.x * blockDim.x + tx) >> 5;
    int nw   = (gridDim.x * blockDim.x) >> 5;
    float bo2v = bo2[0];
    float local = 0.0f;

    for (int n = gw; n < NN; n += nw) {
        const float* hr = g_h + n * HIDD;
        float a0 = 0.f, a1 = 0.f;
        #pragma unroll 8
        for (int k = 0; k < HIDD; k++) {
            float hk = __ldg(hr + k);
            a0 += hk * Wo1s[k * 64 + lane];
            a1 += hk * Wo1s[k * 64 + lane + 32];
        }
        float en = sspf(a0 + bo1s[lane]) * Wo2s[lane]
                 + sspf(a1 + bo1s[lane + 32]) * Wo2s[lane + 32];
        #pragma unroll
        for (int o = 16; o > 0; o >>= 1) en += __shfl_down_sync(0xffffffffu, en, o);
        if (lane == 0) local += en + bo2v;
    }
    if (lane == 0) atomicAdd(&g_sum, local);
}

__global__ void k_fin(float* __restrict__ out)
{
    out[0] = fmaxf(g_sum, 0.0f);
}

// ---------------- launch ---------------------------------------------------
extern "C" void kernel_launch(void* const* d_in, const int* in_sizes, int n_in,
                              void* d_out, int out_size)
{
    const int*   z   = (const int*)d_in[0];
    const float* pos = (const float*)d_in[1];
    const int*   ei  = (const int*)d_in[2];
    const float* emb = (const float*)d_in[3];
    const float* Wf1 = (const float*)d_in[4];
    const float* bf1 = (const float*)d_in[5];
    const float* Wf2 = (const float*)d_in[6];
    const float* bf2 = (const float*)d_in[7];
    const float* Wl1 = (const float*)d_in[8];
    const float* Wl2 = (const float*)d_in[9];
    const float* bl2 = (const float*)d_in[10];
    const float* Wl  = (const float*)d_in[11];
    const float* bl  = (const float*)d_in[12];
    const float* Wo1 = (const float*)d_in[13];
    const float* bo1 = (const float*)d_in[14];
    const float* Wo2 = (const float*)d_in[15];
    const float* bo2 = (const float*)d_in[16];

    float *ph, *px, *pagg, *ptab;
    cudaGetSymbolAddress((void**)&ph,   g_h);
    cudaGetSymbolAddress((void**)&px,   g_x);
    cudaGetSymbolAddress((void**)&pagg, g_agg);
    cudaGetSymbolAddress((void**)&ptab, g_table);

    const size_t SMEM_GEMM = (16384 + 4096) * sizeof(float);       // 80 KB
    const size_t SMEM_TBL  = (16384 + 6400 + 64 + 128) * sizeof(float);  // ~90 KB
    cudaFuncSetAttribute(k_table,   cudaFuncAttributeMaxDynamicSharedMemorySize, (int)SMEM_TBL);
    cudaFuncSetAttribute(k_gemm<0>, cudaFuncAttributeMaxDynamicSharedMemorySize, (int)SMEM_GEMM);
    cudaFuncSetAttribute(k_gemm<1>, cudaFuncAttributeMaxDynamicSharedMemorySize, (int)SMEM_GEMM);
    cudaFuncSetAttribute(k_gemm<2>, cudaFuncAttributeMaxDynamicSharedMemorySize, (int)SMEM_GEMM);

    k_prep<<<2048, 256>>>(pos, ei, z, emb);
    k_table<<<NIT * (KNOTS / KPB), 128, SMEM_TBL>>>(Wf1, bf1, Wf2, bf2);

    for (int i = 0; i < NIT; i++) {
        // x = h @ Wl1[i]; agg = 0
        k_gemm<0><<<NN / 32, 256, SMEM_GEMM>>>(ph, Wl1 + i * HIDD * HIDD, nullptr, px, pagg);
        // msg/scatter with tabulated filter
        k_edge<<<4096, 256>>>(ei, ptab + (size_t)i * KNOTS * HIDD);
        // t = ssp(agg @ Wl2[i] + bl2[i])   (reuse g_x)
        k_gemm<1><<<NN / 32, 256, SMEM_GEMM>>>(pagg, Wl2 + i * HIDD * HIDD, bl2 + i * HIDD, px, nullptr);
        // h += t @ Wl[i] + bl[i]
        k_gemm<2><<<NN / 32, 256, SMEM_GEMM>>>(px, Wl + i * HIDD * HIDD, bl + i * HIDD, ph, nullptr);
    }

    k_readout<<<256, 256>>>(Wo1, bo1, Wo2, bo2);
    k_fin<<<1, 1>>>((float*)d_out);
}

// round 7
// speedup vs baseline: 1.0230x; 1.0230x over previous
#include <cuda_runtime.h>
#include <cuda_bf16.h>
#include <math.h>

#define NN     16384
#define EE     262144
#define HIDD   128
#define NG     50
#define NIT    6
#define KNOTS  4096
#define KPB    32

#define LOG2_F 0.6931471805599453f

typedef unsigned long long ull;

// ---------------- scratch (device globals; no allocation allowed) ----------
static __device__ float g_d[EE];                       // edge distances
static __device__ float g_table[NIT * KNOTS * HIDD];   // Wfilt(d)*C(d) tables, 12.6 MB
static __device__ float g_h[NN * HIDD];
static __device__ float g_x[NN * HIDD];
static __device__ float g_agg[NN * HIDD];
static __device__ float g_sum;

__device__ __forceinline__ float sspf(float x) {
    // shifted softplus: log(1+exp(x)) - log(2), numerically stable
    return fmaxf(x, 0.0f) + log1pf(expf(-fabsf(x))) - LOG2_F;
}

// packed f32x2 helpers (ptxas never auto-fuses; must come from PTX)
__device__ __forceinline__ ull pk2(float a) {
    ull r; asm("mov.b64 %0, {%1, %1};" : "=l"(r) : "f"(a)); return r;
}
__device__ __forceinline__ void ffma2(ull& d, ull a, ull b) {
    asm("fma.rn.f32x2 %0, %1, %2, %0;" : "+l"(d) : "l"(a), "l"(b));
}
__device__ __forceinline__ float2 up2(ull v) {
    float2 r; asm("mov.b64 {%0, %1}, %2;" : "=f"(r.x), "=f"(r.y) : "l"(v)); return r;
}

// ---------------- prep: distances, embedding gather ------------------------
__global__ void k_prep(const float* __restrict__ pos, const int* __restrict__ ei,
                       const int* __restrict__ z, const float* __restrict__ emb)
{
    int t = blockIdx.x * blockDim.x + threadIdx.x;
    int stride = gridDim.x * blockDim.x;
    if (t == 0) g_sum = 0.0f;
    for (int e = t; e < EE; e += stride) {
        int s = ei[e], d = ei[EE + e];
        float dx = pos[3 * s + 0] - pos[3 * d + 0];
        float dy = pos[3 * s + 1] - pos[3 * d + 1];
        float dz = pos[3 * s + 2] - pos[3 * d + 2];
        g_d[e] = sqrtf(dx * dx + dy * dy + dz * dz);
    }
    // embedding gather, float4-vectorized: 32 quads per node row
    const float4* emb4 = (const float4*)emb;
    float4*       h4   = (float4*)g_h;
    for (int q = t; q < NN * 32; q += stride) {
        int n = q >> 5;
        h4[q] = emb4[z[n] * 32 + (q & 31)];
    }
}

// ---------------- filter table build: Wfilt_i(knot) * C(knot) --------------
__global__ void k_table(const float* __restrict__ Wf1, const float* __restrict__ bf1,
                        const float* __restrict__ Wf2, const float* __restrict__ bf2)
{
    extern __shared__ float sm[];
    float* Wf2s = sm;                 // 128*128
    float* Wf1s = sm + 16384;         // 50*128
    float* eaS  = sm + 16384 + 6400;  // 64
    float* hidS = eaS + 64;           // 128

    const int chunks = KNOTS / KPB;
    int i     = blockIdx.x / chunks;
    int chunk = blockIdx.x % chunks;
    int tx = threadIdx.x;

    const float* Wf1g = Wf1 + i * NG * HIDD;
    const float* Wf2g = Wf2 + i * HIDD * HIDD;
    for (int k = tx; k < NG * HIDD; k += 128)   Wf1s[k] = Wf1g[k];
    for (int k = tx; k < HIDD * HIDD; k += 128) Wf2s[k] = Wf2g[k];
    float bf1v = bf1[i * HIDD + tx];
    float bf2v = bf2[i * HIDD + tx];
    __syncthreads();

    const float DELTA = 10.0f / 49.0f;
    const float COEFF = -0.5f / (DELTA * DELTA);
    const float KSTEP = 10.0f / (float)(KNOTS - 1);

    for (int kk = 0; kk < KPB; kk++) {
        int knot = chunk * KPB + kk;
        float xk = knot * KSTEP;
        if (tx < NG) {
            float dd = xk - tx * DELTA;
            eaS[tx] = expf(COEFF * dd * dd);
        }
        __syncthreads();
        float acc = bf1v;
        #pragma unroll
        for (int g = 0; g < NG; g++) acc += eaS[g] * Wf1s[g * HIDD + tx];
        hidS[tx] = sspf(acc);
        __syncthreads();
        float acc2 = bf2v;
        #pragma unroll 16
        for (int k = 0; k < HIDD; k++) acc2 += hidS[k] * Wf2s[k * HIDD + tx];
        float Cx = 0.5f * (cosf(xk * 0.31415926535897932f) + 1.0f);
        g_table[(i * KNOTS + knot) * HIDD + tx] = acc2 * Cx;
        __syncthreads();
    }
}

// ---------------- 128x128 GEMM, row-tile 32, 256 threads, packed f32x2 -----
// Thread (eg,cg): rows eg*4..eg*4+3, cols cg*4..cg*4+3 (accumulated as 2 f32x2).
// MODE 0: out = A@W            (no bias)  + zero zbuf tile
// MODE 1: out = ssp(A@W + b)
// MODE 2: out += A@W + b
template <int MODE>
__global__ void k_gemm(const float* __restrict__ A, const float* __restrict__ W,
                       const float* __restrict__ bias, float* __restrict__ out,
                       float* __restrict__ zbuf)
{
    extern __shared__ float sm[];
    float* Ws = sm;           // 128*128  (row-major [k][col])
    float* As = sm + 16384;   // 32*128   (row-major [row][k])
    int tx = threadIdx.x;

    {   // load W (4096 float4)
        float4* Wd = (float4*)Ws;
        const float4* Wg = (const float4*)W;
        #pragma unroll
        for (int i = 0; i < 16; i++) Wd[tx + 256 * i] = Wg[tx + 256 * i];
    }
    int tile = blockIdx.x;  // grid == NN/32
    {   // load A tile (1024 float4)
        float4* Ad = (float4*)As;
        const float4* Ag = (const float4*)(A + tile * 32 * HIDD);
        #pragma unroll
        for (int i = 0; i < 4; i++) Ad[tx + 256 * i] = Ag[tx + 256 * i];
    }
    __syncthreads();

    int cg = tx & 31;   // column quad: cols cg*4 .. cg*4+3
    int eg = tx >> 5;   // row group: rows eg*4 + t
    const ulonglong2* Ws2 = (const ulonglong2*)Ws;              // [k][32 quads] as 2x f32x2
    const float4*     As4 = (const float4*)As + (eg * 4) * 32;  // row pitch 32 float4

    ull acc[4][2];
    #pragma unroll
    for (int t = 0; t < 4; t++) { acc[t][0] = 0ull; acc[t][1] = 0ull; }

    #pragma unroll 4
    for (int k4 = 0; k4 < 32; k4++) {
        float4 a0 = As4[0 * 32 + k4];
        float4 a1 = As4[1 * 32 + k4];
        float4 a2 = As4[2 * 32 + k4];
        float4 a3 = As4[3 * 32 + k4];
        #pragma unroll
        for (int j = 0; j < 4; j++) {
            ulonglong2 w = Ws2[(4 * k4 + j) * 32 + cg];
            ull p0 = pk2(((const float*)&a0)[j]);
            ull p1 = pk2(((const float*)&a1)[j]);
            ull p2 = pk2(((const float*)&a2)[j]);
            ull p3 = pk2(((const float*)&a3)[j]);
            ffma2(acc[0][0], p0, w.x); ffma2(acc[0][1], p0, w.y);
            ffma2(acc[1][0], p1, w.x); ffma2(acc[1][1], p1, w.y);
            ffma2(acc[2][0], p2, w.x); ffma2(acc[2][1], p2, w.y);
            ffma2(acc[3][0], p3, w.x); ffma2(acc[3][1], p3, w.y);
        }
    }

    float4 b4 = make_float4(0.f, 0.f, 0.f, 0.f);
    if (MODE > 0) b4 = ((const float4*)bias)[cg];

    #pragma unroll
    for (int t = 0; t < 4; t++) {
        int r = tile * 32 + eg * 4 + t;
        float4* o4 = (float4*)(out + r * HIDD) + cg;
        float2 lo = up2(acc[t][0]);
        float2 hi = up2(acc[t][1]);
        float4 v = make_float4(lo.x, lo.y, hi.x, hi.y);
        if (MODE == 0) {
            *o4 = v;
        } else if (MODE == 1) {
            float4 r4;
            r4.x = sspf(v.x + b4.x); r4.y = sspf(v.y + b4.y);
            r4.z = sspf(v.z + b4.z); r4.w = sspf(v.w + b4.w);
            *o4 = r4;
        } else {
            float4 p = *o4;
            p.x += v.x + b4.x; p.y += v.y + b4.y;
            p.z += v.z + b4.z; p.w += v.w + b4.w;
            *o4 = p;
        }
    }
    if (MODE == 0) {
        float4* zb = (float4*)(zbuf + tile * 32 * HIDD);
        float4 z4 = make_float4(0.f, 0.f, 0.f, 0.f);
        #pragma unroll
        for (int i = 0; i < 4; i++) zb[tx + 256 * i] = z4;
    }
}

// ---------------- edge kernel: lerp filter, gather x[src], scatter agg[dst]
// Two edges per warp iteration; ALL loads issued before the first RED so the
// asm-"memory" clobber cannot serialize the second edge's loads behind RED #1.
__global__ void k_edge(const int* __restrict__ ei, const float* __restrict__ tab)
{
    int gw   = (blockIdx.x * blockDim.x + threadIdx.x) >> 5;
    int lane = threadIdx.x & 31;
    int nw   = (gridDim.x * blockDim.x) >> 5;
    const float scale = (float)(KNOTS - 1) / 10.0f;

    for (int e = gw; e < EE; e += 2 * nw) {
        int e2 = e + nw;                    // grid sized so e2 < EE always
        // ---- load phase (both edges) ----
        float d1 = __ldg(&g_d[e]);
        float d2 = __ldg(&g_d[e2]);
        int s1   = __ldg(&ei[e]);
        int s2   = __ldg(&ei[e2]);
        int dst1 = __ldg(&ei[EE + e]);
        int dst2 = __ldg(&ei[EE + e2]);

        float u1 = d1 * scale;
        int  i1 = (int)u1; if (i1 > KNOTS - 2) i1 = KNOTS - 2;
        float f1 = u1 - (float)i1;
        float u2 = d2 * scale;
        int  i2 = (int)u2; if (i2 > KNOTS - 2) i2 = KNOTS - 2;
        float f2 = u2 - (float)i2;

        const float4* ta = (const float4*)(tab + i1 * HIDD);
        const float4* tb = (const float4*)(tab + i2 * HIDD);
        float4 w0a = ta[lane];
        float4 w1a = ta[lane + 32];
        float4 xva = ((const float4*)(g_x + s1 * HIDD))[lane];
        float4 w0b = tb[lane];
        float4 w1b = tb[lane + 32];
        float4 xvb = ((const float4*)(g_x + s2 * HIDD))[lane];

        // ---- compute + scatter phase ----
        float4 ma, mb;
        ma.x = fmaf(f1, w1a.x - w0a.x, w0a.x) * xva.x;
        ma.y = fmaf(f1, w1a.y - w0a.y, w0a.y) * xva.y;
        ma.z = fmaf(f1, w1a.z - w0a.z, w0a.z) * xva.z;
        ma.w = fmaf(f1, w1a.w - w0a.w, w0a.w) * xva.w;
        mb.x = fmaf(f2, w1b.x - w0b.x, w0b.x) * xvb.x;
        mb.y = fmaf(f2, w1b.y - w0b.y, w0b.y) * xvb.y;
        mb.z = fmaf(f2, w1b.z - w0b.z, w0b.z) * xvb.z;
        mb.w = fmaf(f2, w1b.w - w0b.w, w0b.w) * xvb.w;

        float* ar1 = g_agg + dst1 * HIDD + lane * 4;
        float* ar2 = g_agg + dst2 * HIDD + lane * 4;
        asm volatile("red.global.add.v4.f32 [%0], {%1, %2, %3, %4};"
                     :: "l"(ar1), "f"(ma.x), "f"(ma.y), "f"(ma.z), "f"(ma.w) : "memory");
        asm volatile("red.global.add.v4.f32 [%0], {%1, %2, %3, %4};"
                     :: "l"(ar2), "f"(mb.x), "f"(mb.y), "f"(mb.z), "f"(mb.w) : "memory");
    }
}

// ---------------- readout: per-node MLP + global sum -----------------------
__global__ void k_readout(const float* __restrict__ Wo1, const float* __restrict__ bo1,
                          const float* __restrict__ Wo2, const float* __restrict__ bo2)
{
    __shared__ float Wo1s[HIDD * 64];
    __shared__ float Wo2s[64];
    __shared__ float bo1s[64];
    int tx = threadIdx.x;
    for (int k = tx; k < HIDD * 64; k += 256) Wo1s[k] = Wo1[k];
    if (tx < 64) { Wo2s[tx] = Wo2[tx]; bo1s[tx] = bo1[tx]; }
    __syncthreads();

    int lane = tx & 31;
    int gw   = (blockIdx.x * blockDim.x + tx) >> 5;
    int nw   = (gridDim.x * blockDim.x) >> 5;
    float bo2v = bo2[0];
    float local = 0.0f;

    for (int n = gw; n < NN; n += nw) {
        const float* hr = g_h + n * HIDD;
        float a0 = 0.f, a1 = 0.f;
        #pragma unroll 8
        for (int k = 0; k < HIDD; k++) {
            float hk = __ldg(hr + k);
            a0 += hk * Wo1s[k * 64 + lane];
            a1 += hk * Wo1s[k * 64 + lane + 32];
        }
        float en = sspf(a0 + bo1s[lane]) * Wo2s[lane]
                 + sspf(a1 + bo1s[lane + 32]) * Wo2s[lane + 32];
        #pragma unroll
        for (int o = 16; o > 0; o >>= 1) en += __shfl_down_sync(0xffffffffu, en, o);
        if (lane == 0) local += en + bo2v;
    }
    if (lane == 0) atomicAdd(&g_sum, local);
}

__global__ void k_fin(float* __restrict__ out)
{
    out[0] = fmaxf(g_sum, 0.0f);
}

// ---------------- launch ---------------------------------------------------
extern "C" void kernel_launch(void* const* d_in, const int* in_sizes, int n_in,
                              void* d_out, int out_size)
{
    const int*   z   = (const int*)d_in[0];
    const float* pos = (const float*)d_in[1];
    const int*   ei  = (const int*)d_in[2];
    const float* emb = (const float*)d_in[3];
    const float* Wf1 = (const float*)d_in[4];
    const float* bf1 = (const float*)d_in[5];
    const float* Wf2 = (const float*)d_in[6];
    const float* bf2 = (const float*)d_in[7];
    const float* Wl1 = (const float*)d_in[8];
    const float* Wl2 = (const float*)d_in[9];
    const float* bl2 = (const float*)d_in[10];
    const float* Wl  = (const float*)d_in[11];
    const float* bl  = (const float*)d_in[12];
    const float* Wo1 = (const float*)d_in[13];
    const float* bo1 = (const float*)d_in[14];
    const float* Wo2 = (const float*)d_in[15];
    const float* bo2 = (const float*)d_in[16];

    float *ph, *px, *pagg, *ptab;
    cudaGetSymbolAddress((void**)&ph,   g_h);
    cudaGetSymbolAddress((void**)&px,   g_x);
    cudaGetSymbolAddress((void**)&pagg, g_agg);
    cudaGetSymbolAddress((void**)&ptab, g_table);

    const size_t SMEM_GEMM = (16384 + 4096) * sizeof(float);       // 80 KB
    const size_t SMEM_TBL  = (16384 + 6400 + 64 + 128) * sizeof(float);  // ~90 KB
    cudaFuncSetAttribute(k_table,   cudaFuncAttributeMaxDynamicSharedMemorySize, (int)SMEM_TBL);
    cudaFuncSetAttribute(k_gemm<0>, cudaFuncAttributeMaxDynamicSharedMemorySize, (int)SMEM_GEMM);
    cudaFuncSetAttribute(k_gemm<1>, cudaFuncAttributeMaxDynamicSharedMemorySize, (int)SMEM_GEMM);
    cudaFuncSetAttribute(k_gemm<2>, cudaFuncAttributeMaxDynamicSharedMemorySize, (int)SMEM_GEMM);

    k_prep<<<2048, 256>>>(pos, ei, z, emb);
    k_table<<<NIT * (KNOTS / KPB), 128, SMEM_TBL>>>(Wf1, bf1, Wf2, bf2);

    for (int i = 0; i < NIT; i++) {
        // x = h @ Wl1[i]; agg = 0
        k_gemm<0><<<NN / 32, 256, SMEM_GEMM>>>(ph, Wl1 + i * HIDD * HIDD, nullptr, px, pagg);
        // msg/scatter with tabulated filter
        k_edge<<<4096, 256>>>(ei, ptab + (size_t)i * KNOTS * HIDD);
        // t = ssp(agg @ Wl2[i] + bl2[i])   (reuse g_x)
        k_gemm<1><<<NN / 32, 256, SMEM_GEMM>>>(pagg, Wl2 + i * HIDD * HIDD, bl2 + i * HIDD, px, nullptr);
        // h += t @ Wl[i] + bl[i]
        k_gemm<2><<<NN / 32, 256, SMEM_GEMM>>>(px, Wl + i * HIDD * HIDD, bl + i * HIDD, ph, nullptr);
    }

    k_readout<<<256, 256>>>(Wo1, bo1, Wo2, bo2);
    k_fin<<<1, 1>>>((float*)d_out);
}

// round 11
// speedup vs baseline: 1.0264x; 1.0033x over previous
#include <cuda_runtime.h>
#include <cuda_bf16.h>
#include <math.h>
#include <stdint.h>

#define NN     16384
#define EE     262144
#define HIDD   128
#define NG     50
#define NIT    6
#define KNOTS  4096
#define KPB    32
#define GP     130          // As pitch in floats (kills 8-row bank aliasing)

#define LOG2_F 0.6931471805599453f

typedef unsigned long long ull;

// ---------------- scratch (device globals; no allocation allowed) ----------
static __device__ float g_d[EE];                       // edge distances
static __device__ float g_table[NIT * KNOTS * HIDD];   // Wfilt(d)*C(d) tables
static __device__ float g_h[NN * HIDD];
static __device__ float g_x[NN * HIDD];
static __device__ float g_agg[NN * HIDD];
static __device__ float g_sum;

__device__ __forceinline__ float sspf(float x) {
    return fmaxf(x, 0.0f) + log1pf(expf(-fabsf(x))) - LOG2_F;
}

// packed f32x2 helpers (must come from PTX; ptxas never auto-fuses)
__device__ __forceinline__ ull pk2(float a) {
    ull r; asm("mov.b64 %0, {%1, %1};" : "=l"(r) : "f"(a)); return r;
}
__device__ __forceinline__ void ffma2(ull& d, ull a, ull b) {
    asm("fma.rn.f32x2 %0, %1, %2, %0;" : "+l"(d) : "l"(a), "l"(b));
}
__device__ __forceinline__ float2 up2(ull v) {
    float2 r; asm("mov.b64 {%0, %1}, %2;" : "=f"(r.x), "=f"(r.y) : "l"(v)); return r;
}

// ---------------- prep: distances, embedding gather ------------------------
__global__ void k_prep(const float* __restrict__ pos, const int* __restrict__ ei,
                       const int* __restrict__ z, const float* __restrict__ emb)
{
    int t = blockIdx.x * blockDim.x + threadIdx.x;
    int stride = gridDim.x * blockDim.x;
    if (t == 0) g_sum = 0.0f;
    for (int e = t; e < EE; e += stride) {
        int s = ei[e], d = ei[EE + e];
        float dx = pos[3 * s + 0] - pos[3 * d + 0];
        float dy = pos[3 * s + 1] - pos[3 * d + 1];
        float dz = pos[3 * s + 2] - pos[3 * d + 2];
        g_d[e] = sqrtf(dx * dx + dy * dy + dz * dz);
    }
    const float4* emb4 = (const float4*)emb;
    float4*       h4   = (float4*)g_h;
    for (int q = t; q < NN * 32; q += stride) {
        int n = q >> 5;
        h4[q] = emb4[z[n] * 32 + (q & 31)];
    }
}

// ---------------- filter table build: Wfilt_i(knot) * C(knot) --------------
__global__ void k_table(const float* __restrict__ Wf1, const float* __restrict__ bf1,
                        const float* __restrict__ Wf2, const float* __restrict__ bf2)
{
    extern __shared__ float sm[];
    float* Wf2s = sm;                 // 128*128
    float* Wf1s = sm + 16384;         // 50*128
    float* eaS  = sm + 16384 + 6400;  // 64
    float* hidS = eaS + 64;           // 128

    const int chunks = KNOTS / KPB;
    int i     = blockIdx.x / chunks;
    int chunk = blockIdx.x % chunks;
    int tx = threadIdx.x;

    const float* Wf1g = Wf1 + i * NG * HIDD;
    const float* Wf2g = Wf2 + i * HIDD * HIDD;
    for (int k = tx; k < NG * HIDD; k += 128)   Wf1s[k] = Wf1g[k];
    for (int k = tx; k < HIDD * HIDD; k += 128) Wf2s[k] = Wf2g[k];
    float bf1v = bf1[i * HIDD + tx];
    float bf2v = bf2[i * HIDD + tx];
    __syncthreads();

    const float DELTA = 10.0f / 49.0f;
    const float COEFF = -0.5f / (DELTA * DELTA);
    const float KSTEP = 10.0f / (float)(KNOTS - 1);

    for (int kk = 0; kk < KPB; kk++) {
        int knot = chunk * KPB + kk;
        float xk = knot * KSTEP;
        if (tx < NG) {
            float dd = xk - tx * DELTA;
            eaS[tx] = expf(COEFF * dd * dd);
        }
        __syncthreads();
        float acc = bf1v;
        #pragma unroll
        for (int g = 0; g < NG; g++) acc += eaS[g] * Wf1s[g * HIDD + tx];
        hidS[tx] = sspf(acc);
        __syncthreads();
        float acc2 = bf2v;
        #pragma unroll 16
        for (int k = 0; k < HIDD; k++) acc2 += hidS[k] * Wf2s[k * HIDD + tx];
        float Cx = 0.5f * (cosf(xk * 0.31415926535897932f) + 1.0f);
        g_table[(i * KNOTS + knot) * HIDD + tx] = acc2 * Cx;
        __syncthreads();
    }
}

// ------- GEMM v3: 128x128 tile, 256 threads, 8x8 blocks, packed f32x2 ------
// Thread (cy,cx): rows cy*8..+7, cols cx*8..+7.  Per k: 8 broadcast A scalars
// (pitch-130 As, conflict-free) + 2 LDS.128 of W -> 32 FFMA2.
// MODE 0: out = A@W (+ zero zbuf rows); MODE 1: out = ssp(A@W+b); MODE 2: out += A@W+b
template <int MODE>
__global__ void __launch_bounds__(256, 1) k_gemm(
    const float* __restrict__ A, const float* __restrict__ W,
    const float* __restrict__ bias, float* __restrict__ out,
    float* __restrict__ zbuf)
{
    extern __shared__ float sm[];
    float* Ws = sm;            // 128*128 [k][col]
    float* As = sm + 16384;    // 128 rows * pitch 130
    int tx = threadIdx.x;
    int tile = blockIdx.x;     // NN/128 tiles

    {   // W: 4096 float4
        float4* Wd = (float4*)Ws;
        const float4* Wg = (const float4*)W;
        #pragma unroll
        for (int i = 0; i < 16; i++) Wd[tx + 256 * i] = Wg[tx + 256 * i];
    }
    {   // A tile: 8192 float2 -> pitch-130 rows
        const float2* Ag = (const float2*)(A + (size_t)tile * 128 * HIDD);
        #pragma unroll
        for (int i = 0; i < 32; i++) {
            int q = tx + 256 * i;          // 0..8191
            int row = q >> 6, kp = q & 63;
            float2 v = __ldg(&Ag[q]);
            *(float2*)(As + row * GP + kp * 2) = v;
        }
    }
    __syncthreads();

    int cx = tx & 15;   // col block: cols cx*8 .. cx*8+7
    int cy = tx >> 4;   // row block: rows cy*8 .. cy*8+7
    const float*      Ar  = As + cy * 8 * GP;
    const ulonglong2* Ws2 = (const ulonglong2*)Ws;   // [k][16]

    ull acc[8][4];
    #pragma unroll
    for (int i = 0; i < 8; i++)
        #pragma unroll
        for (int j = 0; j < 4; j++) acc[i][j] = 0ull;

    #pragma unroll 2
    for (int k = 0; k < HIDD; k++) {
        ulonglong2 w0 = Ws2[k * 16 + 2 * cx];
        ulonglong2 w1 = Ws2[k * 16 + 2 * cx + 1];
        ull a[8];
        #pragma unroll
        for (int i = 0; i < 8; i++) a[i] = pk2(Ar[i * GP + k]);
        #pragma unroll
        for (int i = 0; i < 8; i++) {
            ffma2(acc[i][0], a[i], w0.x);
            ffma2(acc[i][1], a[i], w0.y);
            ffma2(acc[i][2], a[i], w1.x);
            ffma2(acc[i][3], a[i], w1.y);
        }
    }

    float4 ba = make_float4(0.f, 0.f, 0.f, 0.f);
    float4 bb = make_float4(0.f, 0.f, 0.f, 0.f);
    if (MODE > 0) {
        ba = ((const float4*)bias)[2 * cx];
        bb = ((const float4*)bias)[2 * cx + 1];
    }

    #pragma unroll
    for (int i = 0; i < 8; i++) {
        int r = tile * 128 + cy * 8 + i;
        float4* o4 = (float4*)(out + (size_t)r * HIDD) + 2 * cx;
        float2 p0 = up2(acc[i][0]), p1 = up2(acc[i][1]);
        float2 p2 = up2(acc[i][2]), p3 = up2(acc[i][3]);
        float4 va = make_float4(p0.x, p0.y, p1.x, p1.y);
        float4 vb = make_float4(p2.x, p2.y, p3.x, p3.y);
        if (MODE == 0) {
            o4[0] = va; o4[1] = vb;
        } else if (MODE == 1) {
            float4 r1, r2;
            r1.x = sspf(va.x + ba.x); r1.y = sspf(va.y + ba.y);
            r1.z = sspf(va.z + ba.z); r1.w = sspf(va.w + ba.w);
            r2.x = sspf(vb.x + bb.x); r2.y = sspf(vb.y + bb.y);
            r2.z = sspf(vb.z + bb.z); r2.w = sspf(vb.w + bb.w);
            o4[0] = r1; o4[1] = r2;
        } else {
            float4 q1 = o4[0], q2 = o4[1];
            q1.x += va.x + ba.x; q1.y += va.y + ba.y;
            q1.z += va.z + ba.z; q1.w += va.w + ba.w;
            q2.x += vb.x + bb.x; q2.y += vb.y + bb.y;
            q2.z += vb.z + bb.z; q2.w += vb.w + bb.w;
            o4[0] = q1; o4[1] = q2;
        }
    }
    if (MODE == 0) {
        float4* zb = (float4*)(zbuf + (size_t)tile * 128 * HIDD);
        float4 z4 = make_float4(0.f, 0.f, 0.f, 0.f);
        #pragma unroll
        for (int i = 0; i < 16; i++) zb[tx + 256 * i] = z4;
    }
}

// ---------------- edge kernel (R7-verified: 34.6us) -------------------------
__global__ void k_edge(const int* __restrict__ ei, const float* __restrict__ tab)
{
    int gw   = (blockIdx.x * blockDim.x + threadIdx.x) >> 5;
    int lane = threadIdx.x & 31;
    int nw   = (gridDim.x * blockDim.x) >> 5;
    const float scale = (float)(KNOTS - 1) / 10.0f;

    for (int e = gw; e < EE; e += 2 * nw) {
        int e2 = e + nw;
        float d1 = __ldg(&g_d[e]);
        float d2 = __ldg(&g_d[e2]);
        int s1   = __ldg(&ei[e]);
        int s2   = __ldg(&ei[e2]);
        int dst1 = __ldg(&ei[EE + e]);
        int dst2 = __ldg(&ei[EE + e2]);

        float u1 = d1 * scale;
        int  i1 = (int)u1; if (i1 > KNOTS - 2) i1 = KNOTS - 2;
        float f1 = u1 - (float)i1;
        float u2 = d2 * scale;
        int  i2 = (int)u2; if (i2 > KNOTS - 2) i2 = KNOTS - 2;
        float f2 = u2 - (float)i2;

        const float4* ta = (const float4*)(tab + i1 * HIDD);
        const float4* tb = (const float4*)(tab + i2 * HIDD);
        float4 w0a = ta[lane];
        float4 w1a = ta[lane + 32];
        float4 xva = ((const float4*)(g_x + s1 * HIDD))[lane];
        float4 w0b = tb[lane];
        float4 w1b = tb[lane + 32];
        float4 xvb = ((const float4*)(g_x + s2 * HIDD))[lane];

        float4 ma, mb;
        ma.x = fmaf(f1, w1a.x - w0a.x, w0a.x) * xva.x;
        ma.y = fmaf(f1, w1a.y - w0a.y, w0a.y) * xva.y;
        ma.z = fmaf(f1, w1a.z - w0a.z, w0a.z) * xva.z;
        ma.w = fmaf(f1, w1a.w - w0a.w, w0a.w) * xva.w;
        mb.x = fmaf(f2, w1b.x - w0b.x, w0b.x) * xvb.x;
        mb.y = fmaf(f2, w1b.y - w0b.y, w0b.y) * xvb.y;
        mb.z = fmaf(f2, w1b.z - w0b.z, w0b.z) * xvb.z;
        mb.w = fmaf(f2, w1b.w - w0b.w, w0b.w) * xvb.w;

        float* ar1 = g_agg + dst1 * HIDD + lane * 4;
        float* ar2 = g_agg + dst2 * HIDD + lane * 4;
        asm volatile("red.global.add.v4.f32 [%0], {%1, %2, %3, %4};"
                     :: "l"(ar1), "f"(ma.x), "f"(ma.y), "f"(ma.z), "f"(ma.w) : "memory");
        asm volatile("red.global.add.v4.f32 [%0], {%1, %2, %3, %4};"
                     :: "l"(ar2), "f"(mb.x), "f"(mb.y), "f"(mb.z), "f"(mb.w) : "memory");
    }
}

// ---------------- readout: per-node MLP + global sum -----------------------
__global__ void k_readout(const float* __restrict__ Wo1, const float* __restrict__ bo1,
                          const float* __restrict__ Wo2, const float* __restrict__ bo2)
{
    __shared__ float Wo1s[HIDD * 64];
    __shared__ float Wo2s[64];
    __shared__ float bo1s[64];
    int tx = threadIdx.x;
    for (int k = tx; k < HIDD * 64; k += 256) Wo1s[k] = Wo1[k];
    if (tx < 64) { Wo2s[tx] = Wo2[tx]; bo1s[tx] = bo1[tx]; }
    __syncthreads();

    int lane = tx & 31;
    int gw   = (blockIdx.x * blockDim.x + tx) >> 5;
    int nw   = (gridDim.x * blockDim.x) >> 5;
    float bo2v = bo2[0];
    float local = 0.0f;

    for (int n = gw; n < NN; n += nw) {
        const float* hr = g_h + n * HIDD;
        float a0 = 0.f, a1 = 0.f;
        #pragma unroll 8
        for (int k = 0; k < HIDD; k++) {
            float hk = __ldg(hr + k);
            a0 += hk * Wo1s[k * 64 + lane];
            a1 += hk * Wo1s[k * 64 + lane + 32];
        }
        float en = sspf(a0 + bo1s[lane]) * Wo2s[lane]
                 + sspf(a1 + bo1s[lane + 32]) * Wo2s[lane + 32];
        #pragma unroll
        for (int o = 16; o > 0; o >>= 1) en += __shfl_down_sync(0xffffffffu, en, o);
        if (lane == 0) local += en + bo2v;
    }
    if (lane == 0) atomicAdd(&g_sum, local);
}

__global__ void k_fin(float* __restrict__ out)
{
    out[0] = fmaxf(g_sum, 0.0f);
}

// ---------------- launch ---------------------------------------------------
extern "C" void kernel_launch(void* const* d_in, const int* in_sizes, int n_in,
                              void* d_out, int out_size)
{
    const int*   z   = (const int*)d_in[0];
    const float* pos = (const float*)d_in[1];
    const int*   ei  = (const int*)d_in[2];
    const float* emb = (const float*)d_in[3];
    const float* Wf1 = (const float*)d_in[4];
    const float* bf1 = (const float*)d_in[5];
    const float* Wf2 = (const float*)d_in[6];
    const float* bf2 = (const float*)d_in[7];
    const float* Wl1 = (const float*)d_in[8];
    const float* Wl2 = (const float*)d_in[9];
    const float* bl2 = (const float*)d_in[10];
    const float* Wl  = (const float*)d_in[11];
    const float* bl  = (const float*)d_in[12];
    const float* Wo1 = (const float*)d_in[13];
    const float* bo1 = (const float*)d_in[14];
    const float* Wo2 = (const float*)d_in[15];
    const float* bo2 = (const float*)d_in[16];

    float *ph, *px, *pagg, *ptab;
    cudaGetSymbolAddress((void**)&ph,   g_h);
    cudaGetSymbolAddress((void**)&px,   g_x);
    cudaGetSymbolAddress((void**)&pagg, g_agg);
    cudaGetSymbolAddress((void**)&ptab, g_table);

    const size_t SMEM_GEMM = (16384 + 128 * GP) * sizeof(float);   // ~129 KB
    const size_t SMEM_TBL  = (16384 + 6400 + 64 + 128) * sizeof(float);
    cudaFuncSetAttribute(k_table,   cudaFuncAttributeMaxDynamicSharedMemorySize, (int)SMEM_TBL);
    cudaFuncSetAttribute(k_gemm<0>, cudaFuncAttributeMaxDynamicSharedMemorySize, (int)SMEM_GEMM);
    cudaFuncSetAttribute(k_gemm<1>, cudaFuncAttributeMaxDynamicSharedMemorySize, (int)SMEM_GEMM);
    cudaFuncSetAttribute(k_gemm<2>, cudaFuncAttributeMaxDynamicSharedMemorySize, (int)SMEM_GEMM);

    k_prep<<<2048, 256>>>(pos, ei, z, emb);
    k_table<<<NIT * (KNOTS / KPB), 128, SMEM_TBL>>>(Wf1, bf1, Wf2, bf2);

    for (int i = 0; i < NIT; i++) {
        // x = h @ Wl1[i]; agg = 0
        k_gemm<0><<<NN / 128, 256, SMEM_GEMM>>>(ph, Wl1 + i * HIDD * HIDD, nullptr, px, pagg);
        // msg/scatter with tabulated filter
        k_edge<<<4096, 256>>>(ei, ptab + (size_t)i * KNOTS * HIDD);
        // t = ssp(agg @ Wl2[i] + bl2[i])   (reuse g_x)
        k_gemm<1><<<NN / 128, 256, SMEM_GEMM>>>(pagg, Wl2 + i * HIDD * HIDD, bl2 + i * HIDD, px, nullptr);
        // h += t @ Wl[i] + bl[i]
        k_gemm<2><<<NN / 128, 256, SMEM_GEMM>>>(px, Wl + i * HIDD * HIDD, bl + i * HIDD, ph, nullptr);
    }

    k_readout<<<256, 256>>>(Wo1, bo1, Wo2, bo2);
    k_fin<<<1, 1>>>((float*)d_out);
}